// round 2
// baseline (speedup 1.0000x reference)
#include <cuda_runtime.h>
#include <cstdint>
#include <cstddef>

#define BATCH 64
#define SEQ   512
#define DIM   512
#define HID   256
#define NK    32

typedef unsigned long long u64;

// ---------------- scratch (__device__ globals; no allocation) ----------------
// xp layout: [t][b][g2]  (t*64+b)*2048 + g   -> coalesced sgemm writes, vector lstm reads
__device__ float g_xp[(size_t)SEQ * BATCH * 2048];          // 256 MiB
__device__ float g_hout[(size_t)2 * SEQ * HID * BATCH];     // 64 MiB:  [dir][t][j][b]
__device__ float g_hbuf[2 * 2 * HID * BATCH];               // [dir][buf][k][b]
__device__ unsigned g_bar_count = 0;
__device__ unsigned g_bar_phase = 0;

// ---------------- f32x2 packed-FMA helpers (sm_100a) ----------------
__device__ __forceinline__ u64 ffma2(u64 a, u64 b, u64 c)
{
    u64 d;
    asm("fma.rn.f32x2 %0, %1, %2, %3;" : "=l"(d) : "l"(a), "l"(b), "l"(c));
    return d;
}
__device__ __forceinline__ u64 dup2(float x)
{
    u64 d;
    asm("mov.b64 %0, {%1, %1};" : "=l"(d) : "r"(__float_as_uint(x)));
    return d;
}
__device__ __forceinline__ u64 pack2(float lo, float hi)
{
    u64 d;
    asm("mov.b64 %0, {%1, %2};" : "=l"(d) : "r"(__float_as_uint(lo)), "r"(__float_as_uint(hi)));
    return d;
}
__device__ __forceinline__ float2 unpack2(u64 v)
{
    float2 r;
    asm("mov.b64 {%0, %1}, %2;" : "=f"(r.x), "=f"(r.y) : "l"(v));
    return r;
}

// ---------------- grid barrier (all 128 CTAs co-resident) ----------------
__device__ __forceinline__ void grid_barrier(unsigned nb)
{
    __threadfence();
    __syncthreads();
    if (threadIdx.x == 0) {
        volatile unsigned* vph = &g_bar_phase;
        unsigned ph = *vph;
        unsigned old = atomicAdd(&g_bar_count, 1u);
        if (old == nb - 1u) {
            atomicExch(&g_bar_count, 0u);
            __threadfence();
            atomicAdd(&g_bar_phase, 1u);
        } else {
            while (*vph == ph) { }
        }
    }
    __syncthreads();
}

// ---------------- Kernel 1: xp = x @ [Wih_f;Wih_b]^T + bias (f32x2) ----------------
__global__ __launch_bounds__(256) void sgemm_xp_kernel(
    const float* __restrict__ X, const float* __restrict__ Wf,
    const float* __restrict__ Wb, const float* __restrict__ bf,
    const float* __restrict__ bb)
{
    __shared__ __align__(16) float As[2][8 * 132];
    __shared__ __align__(16) float Bs[2][8 * 132];

    const int nTile = blockIdx.x;   // 0..15
    const int mTile = blockIdx.y;   // 0..255
    const float* W; const float* bias; int nOff;
    if (nTile < 8) { W = Wf; bias = bf; nOff = nTile * 128; }
    else           { W = Wb; bias = bb; nOff = (nTile - 8) * 128; }

    const int tid = threadIdx.x;
    const int lr = tid >> 1;            // 0..127
    const int lc = (tid & 1) * 4;       // 0 or 4
    const float* Aptr = X + (size_t)(mTile * 128 + lr) * DIM + lc;
    const float* Bptr = W + (size_t)(nOff + lr) * DIM + lc;

    const int tx = (tid & 15) * 8;      // n offset within tile
    const int ty = (tid >> 4) * 8;      // m offset within tile

    u64 acc2[4][8];
    const u64 zz = 0ull;
#pragma unroll
    for (int ip = 0; ip < 4; ip++)
#pragma unroll
        for (int j = 0; j < 8; j++) acc2[ip][j] = zz;

    float4 a4 = *(const float4*)Aptr;
    float4 b4 = *(const float4*)Bptr;
    As[0][(lc + 0) * 132 + lr] = a4.x; As[0][(lc + 1) * 132 + lr] = a4.y;
    As[0][(lc + 2) * 132 + lr] = a4.z; As[0][(lc + 3) * 132 + lr] = a4.w;
    Bs[0][(lc + 0) * 132 + lr] = b4.x; Bs[0][(lc + 1) * 132 + lr] = b4.y;
    Bs[0][(lc + 2) * 132 + lr] = b4.z; Bs[0][(lc + 3) * 132 + lr] = b4.w;
    __syncthreads();

    for (int kt = 0; kt < 64; kt++) {
        const int cur = kt & 1;
        if (kt < 63) {
            a4 = *(const float4*)(Aptr + (kt + 1) * 8);
            b4 = *(const float4*)(Bptr + (kt + 1) * 8);
        }
#pragma unroll
        for (int k = 0; k < 8; k++) {
            ulonglong2 aA = *(const ulonglong2*)&As[cur][k * 132 + ty];
            ulonglong2 aB = *(const ulonglong2*)&As[cur][k * 132 + ty + 4];
            float rb[8];
            *(float4*)&rb[0] = *(const float4*)&Bs[cur][k * 132 + tx];
            *(float4*)&rb[4] = *(const float4*)&Bs[cur][k * 132 + tx + 4];
            u64 a2[4]; a2[0] = aA.x; a2[1] = aA.y; a2[2] = aB.x; a2[3] = aB.y;
#pragma unroll
            for (int j = 0; j < 8; j++) {
                u64 bd = dup2(rb[j]);
#pragma unroll
                for (int ip = 0; ip < 4; ip++)
                    acc2[ip][j] = ffma2(a2[ip], bd, acc2[ip][j]);
            }
        }
        if (kt < 63) {
            const int nx = cur ^ 1;
            As[nx][(lc + 0) * 132 + lr] = a4.x; As[nx][(lc + 1) * 132 + lr] = a4.y;
            As[nx][(lc + 2) * 132 + lr] = a4.z; As[nx][(lc + 3) * 132 + lr] = a4.w;
            Bs[nx][(lc + 0) * 132 + lr] = b4.x; Bs[nx][(lc + 1) * 132 + lr] = b4.y;
            Bs[nx][(lc + 2) * 132 + lr] = b4.z; Bs[nx][(lc + 3) * 132 + lr] = b4.w;
            __syncthreads();
        }
    }

    float rbias[8];
#pragma unroll
    for (int j = 0; j < 8; j++) rbias[j] = bias[nOff + tx + j];

#pragma unroll
    for (int ip = 0; ip < 4; ip++) {
        float2 c[8];
#pragma unroll
        for (int j = 0; j < 8; j++) c[j] = unpack2(acc2[ip][j]);
#pragma unroll
        for (int h = 0; h < 2; h++) {
            int mrow = mTile * 128 + ty + 2 * ip + h;
            int bidx = mrow >> 9;
            int tt   = mrow & 511;
            float4 v0, v1;
            if (h == 0) {
                v0.x = c[0].x + rbias[0]; v0.y = c[1].x + rbias[1];
                v0.z = c[2].x + rbias[2]; v0.w = c[3].x + rbias[3];
                v1.x = c[4].x + rbias[4]; v1.y = c[5].x + rbias[5];
                v1.z = c[6].x + rbias[6]; v1.w = c[7].x + rbias[7];
            } else {
                v0.x = c[0].y + rbias[0]; v0.y = c[1].y + rbias[1];
                v0.z = c[2].y + rbias[2]; v0.w = c[3].y + rbias[3];
                v1.x = c[4].y + rbias[4]; v1.y = c[5].y + rbias[5];
                v1.z = c[6].y + rbias[6]; v1.w = c[7].y + rbias[7];
            }
            float* orow = &g_xp[((size_t)tt * 64 + bidx) * 2048 + nTile * 128 + tx];
            *(float4*)orow       = v0;
            *(float4*)(orow + 4) = v1;
        }
    }
}

// ---------------- Kernel 2: persistent biLSTM recurrence (f32x2) ----------------
// 128 CTAs x 128 threads. CTA (dir, s) owns h-indices [4s, 4s+4) => 16 gate rows.
__global__ __launch_bounds__(128) void lstm_kernel(
    const float* __restrict__ Whh_f, const float* __restrict__ Whh_b,
    const int* __restrict__ lengths)
{
    __shared__ __align__(16) float Wsm[16 * 260];
    __shared__ __align__(16) float hsm[2][32 * 64];
    __shared__ float gsm[16 * 64];
    __shared__ float csm[4 * 64];
    __shared__ int   len_sm[64];

    const int tid = threadIdx.x;
    const int cta = blockIdx.x;
    const int dir = cta >> 6;
    const int s   = cta & 63;
    const int s4  = s * 4;
    const float* Whh = dir ? Whh_b : Whh_f;

    for (int idx = tid; idx < 16 * 256; idx += 128) {
        int ri = idx >> 8, k = idx & 255;
        int q = ri >> 2, j = ri & 3;
        Wsm[ri * 260 + k] = Whh[(q * 256 + s4 + j) * 256 + k];
    }
    if (tid < 64) len_sm[tid] = lengths[tid];
    for (int idx = tid; idx < 256; idx += 128) csm[idx] = 0.f;

    {
        float* hb0 = g_hbuf + (dir * 2 + 0) * HID * BATCH;
        for (int idx = tid; idx < 4 * 64; idx += 128) {
            int j = idx >> 6, b = idx & 63;
            hb0[(s4 + j) * 64 + b] = 0.f;
        }
    }
    grid_barrier(gridDim.x);

    const int rp  = tid >> 4;       // 0..7 (row pair)
    const int bq  = tid & 15;       // 0..15 (batch quad)
    const int ri0 = rp * 2, ri1 = rp * 2 + 1;
    int col0;
    { int q0 = ri0 >> 2, j0 = ri0 & 3; col0 = dir * 1024 + q0 * 256 + s4 + j0; }
    // col1 == col0 + 1 (same q, adjacent j)

    for (int st = 0; st < SEQ; st++) {
        const int tstep = dir ? (SEQ - 1 - st) : st;
        const int gbuf  = st & 1;
        const float* hgl  = g_hbuf + (dir * 2 + gbuf) * HID * BATCH;
        float*       hgln = g_hbuf + (dir * 2 + (gbuf ^ 1)) * HID * BATCH;

        // xp init: float2 (col0, col0+1) per batch, packed into batch-pair accumulators
        u64 acc2[2][2];
        {
            float2 x0 = *(const float2*)&g_xp[((size_t)tstep * 64 + (bq * 4 + 0)) * 2048 + col0];
            float2 x1 = *(const float2*)&g_xp[((size_t)tstep * 64 + (bq * 4 + 1)) * 2048 + col0];
            float2 x2 = *(const float2*)&g_xp[((size_t)tstep * 64 + (bq * 4 + 2)) * 2048 + col0];
            float2 x3 = *(const float2*)&g_xp[((size_t)tstep * 64 + (bq * 4 + 3)) * 2048 + col0];
            acc2[0][0] = pack2(x0.x, x1.x); acc2[0][1] = pack2(x2.x, x3.x);
            acc2[1][0] = pack2(x0.y, x1.y); acc2[1][1] = pack2(x2.y, x3.y);
        }

        // chunked, double-buffered h load (8 chunks of 32 k-rows)
        float4 pf[4];
#pragma unroll
        for (int r = 0; r < 4; r++)
            pf[r] = __ldcg(((const float4*)hgl) + tid + r * 128);
#pragma unroll
        for (int r = 0; r < 4; r++) ((float4*)hsm[0])[tid + r * 128] = pf[r];
        __syncthreads();

        for (int cc = 0; cc < 8; cc++) {
            const int cb = cc & 1;
            if (cc < 7) {
#pragma unroll
                for (int r = 0; r < 4; r++)
                    pf[r] = __ldcg(((const float4*)hgl) + (cc + 1) * 512 + tid + r * 128);
            }
            const float* hrow = hsm[cb];
#pragma unroll
            for (int kk = 0; kk < 32; kk += 4) {
                const int kg = cc * 32 + kk;
                float4 w0 = *(const float4*)&Wsm[ri0 * 260 + kg];
                float4 w1 = *(const float4*)&Wsm[ri1 * 260 + kg];
                ulonglong2 h0 = *(const ulonglong2*)&hrow[(kk + 0) * 64 + bq * 4];
                ulonglong2 h1 = *(const ulonglong2*)&hrow[(kk + 1) * 64 + bq * 4];
                ulonglong2 h2 = *(const ulonglong2*)&hrow[(kk + 2) * 64 + bq * 4];
                ulonglong2 h3 = *(const ulonglong2*)&hrow[(kk + 3) * 64 + bq * 4];
                u64 d;
                d = dup2(w0.x); acc2[0][0] = ffma2(d, h0.x, acc2[0][0]); acc2[0][1] = ffma2(d, h0.y, acc2[0][1]);
                d = dup2(w1.x); acc2[1][0] = ffma2(d, h0.x, acc2[1][0]); acc2[1][1] = ffma2(d, h0.y, acc2[1][1]);
                d = dup2(w0.y); acc2[0][0] = ffma2(d, h1.x, acc2[0][0]); acc2[0][1] = ffma2(d, h1.y, acc2[0][1]);
                d = dup2(w1.y); acc2[1][0] = ffma2(d, h1.x, acc2[1][0]); acc2[1][1] = ffma2(d, h1.y, acc2[1][1]);
                d = dup2(w0.z); acc2[0][0] = ffma2(d, h2.x, acc2[0][0]); acc2[0][1] = ffma2(d, h2.y, acc2[0][1]);
                d = dup2(w1.z); acc2[1][0] = ffma2(d, h2.x, acc2[1][0]); acc2[1][1] = ffma2(d, h2.y, acc2[1][1]);
                d = dup2(w0.w); acc2[0][0] = ffma2(d, h3.x, acc2[0][0]); acc2[0][1] = ffma2(d, h3.y, acc2[0][1]);
                d = dup2(w1.w); acc2[1][0] = ffma2(d, h3.x, acc2[1][0]); acc2[1][1] = ffma2(d, h3.y, acc2[1][1]);
            }
            if (cc < 7) {
#pragma unroll
                for (int r = 0; r < 4; r++) ((float4*)hsm[cb ^ 1])[tid + r * 128] = pf[r];
            }
            __syncthreads();
        }

        {
            float2 u;
            u = unpack2(acc2[0][0]); gsm[ri0 * 64 + bq * 4 + 0] = u.x; gsm[ri0 * 64 + bq * 4 + 1] = u.y;
            u = unpack2(acc2[0][1]); gsm[ri0 * 64 + bq * 4 + 2] = u.x; gsm[ri0 * 64 + bq * 4 + 3] = u.y;
            u = unpack2(acc2[1][0]); gsm[ri1 * 64 + bq * 4 + 0] = u.x; gsm[ri1 * 64 + bq * 4 + 1] = u.y;
            u = unpack2(acc2[1][1]); gsm[ri1 * 64 + bq * 4 + 2] = u.x; gsm[ri1 * 64 + bq * 4 + 3] = u.y;
        }
        __syncthreads();

#pragma unroll
        for (int r = 0; r < 2; r++) {
            const int it = tid + r * 128;
            const int j = it >> 6, b = it & 63;
            float gi = gsm[(0 * 4 + j) * 64 + b];
            float gf = gsm[(1 * 4 + j) * 64 + b];
            float gg = gsm[(2 * 4 + j) * 64 + b];
            float go = gsm[(3 * 4 + j) * 64 + b];
            float i_ = 1.f / (1.f + expf(-gi));
            float f_ = 1.f / (1.f + expf(-gf));
            float o_ = 1.f / (1.f + expf(-go));
            float g_ = tanhf(gg);
            float c_old = csm[j * 64 + b];
            float c_new = f_ * c_old + i_ * g_;
            float h_new = o_ * tanhf(c_new);
            bool  m = (tstep < len_sm[b]);
            float h_old = __ldcg(&hgl[(s4 + j) * 64 + b]);
            float c_out = m ? c_new : c_old;
            float h_out = m ? h_new : h_old;
            csm[j * 64 + b] = c_out;
            __stcg(&hgln[(s4 + j) * 64 + b], h_out);
            g_hout[((size_t)(dir * SEQ + tstep) * HID + (s4 + j)) * 64 + b] = h_out;
        }
        grid_barrier(gridDim.x);
    }
}

// ---------------- Kernel 3: logits = [h_f;h_b] @ W_clf^T + b_clf (f32x2) ----------------
__global__ __launch_bounds__(256) void clf_kernel(
    const float* __restrict__ Wclf, const float* __restrict__ bclf,
    float* __restrict__ out)
{
    __shared__ float Ws[32 * 65];
    __shared__ __align__(16) float hs[64 * 64];
    const int t   = blockIdx.x;
    const int tid = threadIdx.x;
    const int n   = tid & 31;
    const int bg  = tid >> 5;     // 0..7 -> batches bg*8..bg*8+7

    u64 acc2[4];
#pragma unroll
    for (int i = 0; i < 4; i++) acc2[i] = 0ull;

    for (int ch = 0; ch < 8; ch++) {
        const int dir = ch >> 2;
        const int jbase = (ch & 3) * 64;
        for (int l = tid; l < 2048; l += 256) {
            int nn = l >> 6, jj = l & 63;
            Ws[nn * 65 + jj] = Wclf[nn * 512 + dir * 256 + jbase + jj];
        }
        const float* hsrc = g_hout + ((size_t)(dir * SEQ + t) * HID + jbase) * 64;
#pragma unroll
        for (int r = 0; r < 4; r++)
            ((float4*)hs)[tid + r * 256] = __ldg(((const float4*)hsrc) + tid + r * 256);
        __syncthreads();
#pragma unroll 16
        for (int jj = 0; jj < 64; jj++) {
            u64 wd = dup2(Ws[n * 65 + jj]);
            ulonglong2 hA = *(const ulonglong2*)&hs[jj * 64 + bg * 8];
            ulonglong2 hB = *(const ulonglong2*)&hs[jj * 64 + bg * 8 + 4];
            acc2[0] = ffma2(wd, hA.x, acc2[0]);
            acc2[1] = ffma2(wd, hA.y, acc2[1]);
            acc2[2] = ffma2(wd, hB.x, acc2[2]);
            acc2[3] = ffma2(wd, hB.y, acc2[3]);
        }
        __syncthreads();
    }
    const float bias = bclf[n];
    float accf[8];
    { float2 u;
      u = unpack2(acc2[0]); accf[0] = u.x; accf[1] = u.y;
      u = unpack2(acc2[1]); accf[2] = u.x; accf[3] = u.y;
      u = unpack2(acc2[2]); accf[4] = u.x; accf[5] = u.y;
      u = unpack2(acc2[3]); accf[6] = u.x; accf[7] = u.y; }
#pragma unroll
    for (int bb = 0; bb < 8; bb++) {
        int b = bg * 8 + bb;
        out[((size_t)b * SEQ + t) * NK + n] = accf[bb] + bias;
    }
}

// ---------------- Kernel 4: Viterbi decode (tree argmax, 1 warp/batch) ----------------
__global__ __launch_bounds__(32) void viterbi_kernel(
    const float* __restrict__ logits, const int* __restrict__ lengths,
    const float* __restrict__ startt, const float* __restrict__ endt,
    const float* __restrict__ trans, float* __restrict__ preds, int write_preds)
{
    __shared__ unsigned char hist[511][32];
    const int b = blockIdx.x;
    const int j = threadIdx.x;
    const int len = lengths[b];

    float tcol[32];
#pragma unroll
    for (int i = 0; i < 32; i++) tcol[i] = trans[i * 32 + j];

    const float* lg = logits + (size_t)b * SEQ * NK;
    float score = startt[j] + lg[j];
    float e_next = lg[NK + j];

    for (int t = 1; t < SEQ; t++) {
        float e = e_next;
        if (t + 1 < SEQ) e_next = lg[(t + 1) * NK + j];

        // level 0: 16 pairs (strict >, first-max tie-break)
        float bv[16]; int bi[16];
#pragma unroll
        for (int i = 0; i < 16; i++) {
            float v0 = __shfl_sync(0xffffffffu, score, 2 * i)     + tcol[2 * i];
            float v1 = __shfl_sync(0xffffffffu, score, 2 * i + 1) + tcol[2 * i + 1];
            bool tt = v1 > v0;
            bv[i] = tt ? v1 : v0;
            bi[i] = tt ? 2 * i + 1 : 2 * i;
        }
#pragma unroll
        for (int s2 = 8; s2 >= 1; s2 >>= 1) {
#pragma unroll
            for (int i = 0; i < 8; i++) {
                if (i < s2) {
                    bool tt = bv[i + s2] > bv[i];
                    bv[i] = tt ? bv[i + s2] : bv[i];
                    bi[i] = tt ? bi[i + s2] : bi[i];
                }
            }
        }
        float nscore = bv[0] + e;
        int   arg    = bi[0];
        bool m = (t < len);
        hist[t - 1][j] = (unsigned char)(m ? arg : j);
        score = m ? nscore : score;
    }
    score += endt[j];

    // first-max argmax across warp (matches jnp.argmax tie-breaking)
    float bvv = score; int bii = j;
#pragma unroll
    for (int off = 16; off; off >>= 1) {
        float ov = __shfl_xor_sync(0xffffffffu, bvv, off);
        int   oi = __shfl_xor_sync(0xffffffffu, bii, off);
        if (ov > bvv || (ov == bvv && oi < bii)) { bvv = ov; bii = oi; }
    }
    __syncwarp();

    if (write_preds && j == 0) {
        int tag = bii;
        float* pp = preds + (size_t)b * SEQ;
        for (int t = SEQ - 2; t >= 0; t--) {
            pp[t + 1] = (float)(((t + 1) < len) ? tag : 0);
            tag = hist[t][tag];
        }
        pp[0] = (float)((0 < len) ? tag : 0);
    }
}

// ---------------- launch ----------------
extern "C" void kernel_launch(void* const* d_in, const int* in_sizes, int n_in,
                              void* d_out, int out_size)
{
    const float* x     = (const float*)d_in[0];
    const int*   lens  = (const int*)d_in[1];
    // d_in[2] = mask (derived from lengths; unused)
    const float* Wih_f = (const float*)d_in[3];
    const float* Whh_f = (const float*)d_in[4];
    const float* b_f   = (const float*)d_in[5];
    const float* Wih_b = (const float*)d_in[6];
    const float* Whh_b = (const float*)d_in[7];
    const float* b_b   = (const float*)d_in[8];
    const float* W_clf = (const float*)d_in[9];
    const float* b_clf = (const float*)d_in[10];
    const float* st_t  = (const float*)d_in[11];
    const float* en_t  = (const float*)d_in[12];
    const float* trans = (const float*)d_in[13];
    float* out = (float*)d_out;

    sgemm_xp_kernel<<<dim3(16, 256), 256>>>(x, Wih_f, Wih_b, b_f, b_b);
    lstm_kernel<<<128, 128>>>(Whh_f, Whh_b, lens);
    clf_kernel<<<512, 256>>>(W_clf, b_clf, out);

    const int logits_elems = BATCH * SEQ * NK;      // 1048576
    const int preds_elems  = BATCH * SEQ;           // 32768
    int wp = (out_size >= logits_elems + preds_elems) ? 1 : 0;
    viterbi_kernel<<<64, 32>>>(out, lens, st_t, en_t, trans, out + logits_elems, wp);
}

// round 4
// speedup vs baseline: 1.2394x; 1.2394x over previous
#include <cuda_runtime.h>
#include <cuda_bf16.h>
#include <cstdint>
#include <cstddef>

#define BATCH 64
#define SEQ   512
#define DIM   512
#define HID   256
#define NK    32

typedef unsigned long long u64;

// ---------------- scratch (__device__ globals; no allocation) ----------------
// xp layout: [t*64+b][g]  ((t*64+b)*2048 + g)
__device__ float g_xp[(size_t)SEQ * BATCH * 2048];          // 256 MiB
__device__ float g_hout[(size_t)2 * SEQ * HID * BATCH];     // 64 MiB:  [dir][t][j][b]
__device__ float g_hbuf[2 * 2 * HID * BATCH];               // [dir][buf][k][b]
__device__ __nv_bfloat16 g_xhi[(size_t)32768 * 512];
__device__ __nv_bfloat16 g_xlo[(size_t)32768 * 512];
__device__ __nv_bfloat16 g_whi[(size_t)2048 * 512];
__device__ __nv_bfloat16 g_wlo[(size_t)2048 * 512];
__device__ unsigned g_bar_count = 0;
__device__ unsigned g_bar_phase = 0;

// ---------------- f32x2 helpers (legal PTX; = fp32 FMA numerics) ----------------
__device__ __forceinline__ u64 ffma2(u64 a, u64 b, u64 c)
{
    u64 d;
    asm("fma.rn.f32x2 %0, %1, %2, %3;" : "=l"(d) : "l"(a), "l"(b), "l"(c));
    return d;
}
__device__ __forceinline__ u64 dup2(float x)
{
    u64 d;
    asm("mov.b64 %0, {%1, %1};" : "=l"(d) : "r"(__float_as_uint(x)));
    return d;
}
__device__ __forceinline__ u64 pack2(float lo, float hi)
{
    u64 d;
    asm("mov.b64 %0, {%1, %2};" : "=l"(d) : "r"(__float_as_uint(lo)), "r"(__float_as_uint(hi)));
    return d;
}
__device__ __forceinline__ float2 unpack2(u64 v)
{
    float2 r;
    asm("mov.b64 {%0, %1}, %2;" : "=f"(r.x), "=f"(r.y) : "l"(v));
    return r;
}

// ---------------- mma.sync / ldmatrix / cp.async helpers (portable PTX) ------
__device__ __forceinline__ uint32_t smem_to_u32(const void* p) {
    uint32_t a;
    asm("{ .reg .u64 t; cvta.to.shared.u64 t, %1; cvt.u32.u64 %0, t; }" : "=r"(a) : "l"(p));
    return a;
}
__device__ __forceinline__ void cp_async16(uint32_t saddr, const void* gptr) {
    asm volatile("cp.async.cg.shared.global [%0], [%1], 16;" :: "r"(saddr), "l"(gptr));
}
#define CP_COMMIT() asm volatile("cp.async.commit_group;")
#define CP_WAIT(n)  asm volatile("cp.async.wait_group %0;" :: "n"(n) : "memory")

__device__ __forceinline__ void ldsm4(uint32_t* r, uint32_t addr) {
    asm volatile("ldmatrix.sync.aligned.m8n8.x4.shared.b16 {%0,%1,%2,%3}, [%4];"
        : "=r"(r[0]), "=r"(r[1]), "=r"(r[2]), "=r"(r[3]) : "r"(addr));
}
__device__ __forceinline__ void mma16816(float* c, const uint32_t* a, uint32_t b0, uint32_t b1) {
    asm volatile("mma.sync.aligned.m16n8k16.row.col.f32.bf16.bf16.f32 "
        "{%0,%1,%2,%3}, {%4,%5,%6,%7}, {%8,%9}, {%0,%1,%2,%3};"
        : "+f"(c[0]), "+f"(c[1]), "+f"(c[2]), "+f"(c[3])
        : "r"(a[0]), "r"(a[1]), "r"(a[2]), "r"(a[3]), "r"(b0), "r"(b1));
}

// ---------------- grid barrier ----------------
__device__ __forceinline__ void grid_barrier(unsigned nb)
{
    __threadfence();
    __syncthreads();
    if (threadIdx.x == 0) {
        volatile unsigned* vph = &g_bar_phase;
        unsigned ph = *vph;
        unsigned old = atomicAdd(&g_bar_count, 1u);
        if (old == nb - 1u) {
            atomicExch(&g_bar_count, 0u);
            __threadfence();
            atomicAdd(&g_bar_phase, 1u);
        } else {
            while (*vph == ph) { }
        }
    }
    __syncthreads();
}

// ---------------- Kernel 0: fp32 -> bf16 hi/lo split ----------------
__global__ __launch_bounds__(256) void split_kernel(
    const float* __restrict__ src, __nv_bfloat16* __restrict__ hi,
    __nv_bfloat16* __restrict__ lo, int n)
{
    int stride = gridDim.x * blockDim.x;
    for (int i = blockIdx.x * blockDim.x + threadIdx.x; i < n; i += stride) {
        float v = src[i];
        __nv_bfloat16 h = __float2bfloat16(v);
        float hv = __bfloat162float(h);
        __nv_bfloat16 l = __float2bfloat16(v - hv);
        hi[i] = h; lo[i] = l;
    }
}

// ---------------- Kernel 1: bf16 3-split GEMM via mma.sync ----------------
// xp = x @ [Wih_f;Wih_b]^T + bias.  A=x(32768x512), B=W(2048x512), TN, K=512.
// CTA tile 128x128, 8 warps of 64x32, KC=16, double-buffered cp.async.
// smem stage (16KB): Ah@0, Al@4K, Bh@8K, Bl@12K; each 128 rows x 32B, 16B-chunk
// swizzle: c' = c ^ ((row>>2)&1).
#define NCHUNK 32
__global__ __launch_bounds__(256) void gemm_xp_mma_kernel(
    const float* __restrict__ bf_, const float* __restrict__ bb_)
{
    __shared__ __align__(128) char sm[2][16384];
    __shared__ float s_bias[128];

    const int tid  = threadIdx.x;
    const int lane = tid & 31;
    const int wid  = tid >> 5;
    const int wm   = wid >> 2;      // 0..1
    const int wn   = wid & 3;       // 0..3
    const int nTile = blockIdx.x;   // 0..15
    const int mTile = blockIdx.y;   // 0..255
    const int mBase = mTile * 128;
    const int nBase = nTile * 128;

    if (tid < 128) {
        const float* bsrc = (nTile < 8) ? bf_ : bb_;
        int boff = (nTile < 8) ? nTile * 128 : (nTile - 8) * 128;
        s_bias[tid] = bsrc[boff + tid];
    }

    const uint32_t smem_base = smem_to_u32(sm);

    // per-thread ldmatrix offsets (within a stage)
    uint32_t aoff[2][4];   // [split][mf]
    {
        const int arow = wm * 64 + (lane & 15);
        const int akc  = lane >> 4;
#pragma unroll
        for (int mf = 0; mf < 4; mf++) {
            const int r = arow + mf * 16;
            const uint32_t o = (uint32_t)(r * 32 + ((akc ^ ((r >> 2) & 1)) << 4));
            aoff[0][mf] = o;            // Ah
            aoff[1][mf] = o + 4096u;    // Al
        }
    }
    uint32_t boff[2][2];   // [split][p]
    {
        const int nrow = wn * 32 + (lane & 7) + ((lane >> 4) << 3);
        const int bkc  = (lane >> 3) & 1;
#pragma unroll
        for (int p = 0; p < 2; p++) {
            const int r = nrow + p * 16;
            const uint32_t o = (uint32_t)(r * 32 + ((bkc ^ ((r >> 2) & 1)) << 4));
            boff[0][p] = o + 8192u;     // Bh
            boff[1][p] = o + 12288u;    // Bl
        }
    }

    // cp.async source setup: each thread moves one 16B chunk per tensor per stage
    const int ldrow = tid >> 1;
    const int ldck  = tid & 1;
    const uint32_t ld_soff = (uint32_t)(ldrow * 32 + ((ldck ^ ((ldrow >> 2) & 1)) << 4));
    const __nv_bfloat16* Ahg = g_xhi + (size_t)(mBase + ldrow) * 512 + ldck * 8;
    const __nv_bfloat16* Alg = g_xlo + (size_t)(mBase + ldrow) * 512 + ldck * 8;
    const __nv_bfloat16* Bhg = g_whi + (size_t)(nBase + ldrow) * 512 + ldck * 8;
    const __nv_bfloat16* Blg = g_wlo + (size_t)(nBase + ldrow) * 512 + ldck * 8;

    float cr[4][4][4];
#pragma unroll
    for (int mf = 0; mf < 4; mf++)
#pragma unroll
        for (int nf = 0; nf < 4; nf++)
#pragma unroll
            for (int q = 0; q < 4; q++) cr[mf][nf][q] = 0.f;

    // prologue: stage 0
    {
        const uint32_t so = smem_base + ld_soff;
        cp_async16(so,          Ahg);
        cp_async16(so + 4096u,  Alg);
        cp_async16(so + 8192u,  Bhg);
        cp_async16(so + 12288u, Blg);
        CP_COMMIT();
    }

    for (int c = 0; c < NCHUNK; c++) {
        if (c + 1 < NCHUNK) {
            const int kb = (c + 1) * 16;
            const uint32_t so = smem_base + ((c + 1) & 1) * 16384u + ld_soff;
            cp_async16(so,          Ahg + kb);
            cp_async16(so + 4096u,  Alg + kb);
            cp_async16(so + 8192u,  Bhg + kb);
            cp_async16(so + 12288u, Blg + kb);
            CP_COMMIT();
            CP_WAIT(1);
        } else {
            CP_WAIT(0);
        }
        __syncthreads();

        const uint32_t stg = smem_base + (c & 1) * 16384u;

        uint32_t ah[4][4];
#pragma unroll
        for (int mf = 0; mf < 4; mf++) ldsm4(ah[mf], stg + aoff[0][mf]);
        uint32_t bh[2][4];
#pragma unroll
        for (int p = 0; p < 2; p++) ldsm4(bh[p], stg + boff[0][p]);
#pragma unroll
        for (int mf = 0; mf < 4; mf++)
#pragma unroll
            for (int nf = 0; nf < 4; nf++)
                mma16816(cr[mf][nf], ah[mf], bh[nf >> 1][2 * (nf & 1)], bh[nf >> 1][2 * (nf & 1) + 1]);

        uint32_t bl[2][4];
#pragma unroll
        for (int p = 0; p < 2; p++) ldsm4(bl[p], stg + boff[1][p]);
#pragma unroll
        for (int mf = 0; mf < 4; mf++)
#pragma unroll
            for (int nf = 0; nf < 4; nf++)
                mma16816(cr[mf][nf], ah[mf], bl[nf >> 1][2 * (nf & 1)], bl[nf >> 1][2 * (nf & 1) + 1]);

        uint32_t al[4][4];
#pragma unroll
        for (int mf = 0; mf < 4; mf++) ldsm4(al[mf], stg + aoff[1][mf]);
#pragma unroll
        for (int mf = 0; mf < 4; mf++)
#pragma unroll
            for (int nf = 0; nf < 4; nf++)
                mma16816(cr[mf][nf], al[mf], bh[nf >> 1][2 * (nf & 1)], bh[nf >> 1][2 * (nf & 1) + 1]);

        __syncthreads();
    }

    // epilogue: bias + store to g_xp[(t*64+b)*2048 + n], m = b*512+t
#pragma unroll
    for (int mf = 0; mf < 4; mf++) {
        const int m0 = mBase + wm * 64 + mf * 16 + (lane >> 2);
        const int m1 = m0 + 8;
        const size_t r0 = ((size_t)(m0 & 511) * 64 + (m0 >> 9)) * 2048;
        const size_t r1 = ((size_t)(m1 & 511) * 64 + (m1 >> 9)) * 2048;
#pragma unroll
        for (int nf = 0; nf < 4; nf++) {
            const int nl = wn * 32 + nf * 8 + (lane & 3) * 2;
            const float b0 = s_bias[nl], b1 = s_bias[nl + 1];
            const int n = nBase + nl;
            float2 v0 = make_float2(cr[mf][nf][0] + b0, cr[mf][nf][1] + b1);
            float2 v1 = make_float2(cr[mf][nf][2] + b0, cr[mf][nf][3] + b1);
            *(float2*)&g_xp[r0 + n] = v0;
            *(float2*)&g_xp[r1 + n] = v1;
        }
    }
}

// ---------------- Kernel 2: persistent biLSTM recurrence ----------------
__global__ __launch_bounds__(128) void lstm_kernel(
    const float* __restrict__ Whh_f, const float* __restrict__ Whh_b,
    const int* __restrict__ lengths)
{
    __shared__ __align__(16) float Wsm[16 * 260];
    __shared__ __align__(16) float hsm[2][32 * 64];
    __shared__ float gsm[16 * 64];
    __shared__ float csm[4 * 64];
    __shared__ int   len_sm[64];

    const int tid = threadIdx.x;
    const int cta = blockIdx.x;
    const int dir = cta >> 6;
    const int s   = cta & 63;
    const int s4  = s * 4;
    const float* Whh = dir ? Whh_b : Whh_f;

    for (int idx = tid; idx < 16 * 256; idx += 128) {
        int ri = idx >> 8, k = idx & 255;
        int q = ri >> 2, j = ri & 3;
        Wsm[ri * 260 + k] = Whh[(q * 256 + s4 + j) * 256 + k];
    }
    if (tid < 64) len_sm[tid] = lengths[tid];
    for (int idx = tid; idx < 256; idx += 128) csm[idx] = 0.f;

    {
        float* hb0 = g_hbuf + (dir * 2 + 0) * HID * BATCH;
        for (int idx = tid; idx < 4 * 64; idx += 128) {
            int j = idx >> 6, b = idx & 63;
            hb0[(s4 + j) * 64 + b] = 0.f;
        }
    }
    grid_barrier(gridDim.x);

    const int rp  = tid >> 4;
    const int bq  = tid & 15;
    const int ri0 = rp * 2, ri1 = rp * 2 + 1;
    int col0;
    { int q0 = ri0 >> 2, j0 = ri0 & 3; col0 = dir * 1024 + q0 * 256 + s4 + j0; }

    for (int st = 0; st < SEQ; st++) {
        const int tstep = dir ? (SEQ - 1 - st) : st;
        const int gbuf  = st & 1;
        const float* hgl  = g_hbuf + (dir * 2 + gbuf) * HID * BATCH;
        float*       hgln = g_hbuf + (dir * 2 + (gbuf ^ 1)) * HID * BATCH;

        u64 acc2[2][2];
        {
            float2 x0 = *(const float2*)&g_xp[((size_t)tstep * 64 + (bq * 4 + 0)) * 2048 + col0];
            float2 x1 = *(const float2*)&g_xp[((size_t)tstep * 64 + (bq * 4 + 1)) * 2048 + col0];
            float2 x2 = *(const float2*)&g_xp[((size_t)tstep * 64 + (bq * 4 + 2)) * 2048 + col0];
            float2 x3 = *(const float2*)&g_xp[((size_t)tstep * 64 + (bq * 4 + 3)) * 2048 + col0];
            acc2[0][0] = pack2(x0.x, x1.x); acc2[0][1] = pack2(x2.x, x3.x);
            acc2[1][0] = pack2(x0.y, x1.y); acc2[1][1] = pack2(x2.y, x3.y);
        }

        float4 pf[4];
#pragma unroll
        for (int r = 0; r < 4; r++)
            pf[r] = __ldcg(((const float4*)hgl) + tid + r * 128);
#pragma unroll
        for (int r = 0; r < 4; r++) ((float4*)hsm[0])[tid + r * 128] = pf[r];
        __syncthreads();

        for (int cc = 0; cc < 8; cc++) {
            const int cb = cc & 1;
            if (cc < 7) {
#pragma unroll
                for (int r = 0; r < 4; r++)
                    pf[r] = __ldcg(((const float4*)hgl) + (cc + 1) * 512 + tid + r * 128);
            }
            const float* hrow = hsm[cb];
#pragma unroll
            for (int kk = 0; kk < 32; kk += 4) {
                const int kg = cc * 32 + kk;
                float4 w0 = *(const float4*)&Wsm[ri0 * 260 + kg];
                float4 w1 = *(const float4*)&Wsm[ri1 * 260 + kg];
                ulonglong2 h0 = *(const ulonglong2*)&hrow[(kk + 0) * 64 + bq * 4];
                ulonglong2 h1 = *(const ulonglong2*)&hrow[(kk + 1) * 64 + bq * 4];
                ulonglong2 h2 = *(const ulonglong2*)&hrow[(kk + 2) * 64 + bq * 4];
                ulonglong2 h3 = *(const ulonglong2*)&hrow[(kk + 3) * 64 + bq * 4];
                u64 d;
                d = dup2(w0.x); acc2[0][0] = ffma2(d, h0.x, acc2[0][0]); acc2[0][1] = ffma2(d, h0.y, acc2[0][1]);
                d = dup2(w1.x); acc2[1][0] = ffma2(d, h0.x, acc2[1][0]); acc2[1][1] = ffma2(d, h0.y, acc2[1][1]);
                d = dup2(w0.y); acc2[0][0] = ffma2(d, h1.x, acc2[0][0]); acc2[0][1] = ffma2(d, h1.y, acc2[0][1]);
                d = dup2(w1.y); acc2[1][0] = ffma2(d, h1.x, acc2[1][0]); acc2[1][1] = ffma2(d, h1.y, acc2[1][1]);
                d = dup2(w0.z); acc2[0][0] = ffma2(d, h2.x, acc2[0][0]); acc2[0][1] = ffma2(d, h2.y, acc2[0][1]);
                d = dup2(w1.z); acc2[1][0] = ffma2(d, h2.x, acc2[1][0]); acc2[1][1] = ffma2(d, h2.y, acc2[1][1]);
                d = dup2(w0.w); acc2[0][0] = ffma2(d, h3.x, acc2[0][0]); acc2[0][1] = ffma2(d, h3.y, acc2[0][1]);
                d = dup2(w1.w); acc2[1][0] = ffma2(d, h3.x, acc2[1][0]); acc2[1][1] = ffma2(d, h3.y, acc2[1][1]);
            }
            if (cc < 7) {
#pragma unroll
                for (int r = 0; r < 4; r++) ((float4*)hsm[cb ^ 1])[tid + r * 128] = pf[r];
            }
            __syncthreads();
        }

        {
            float2 u;
            u = unpack2(acc2[0][0]); gsm[ri0 * 64 + bq * 4 + 0] = u.x; gsm[ri0 * 64 + bq * 4 + 1] = u.y;
            u = unpack2(acc2[0][1]); gsm[ri0 * 64 + bq * 4 + 2] = u.x; gsm[ri0 * 64 + bq * 4 + 3] = u.y;
            u = unpack2(acc2[1][0]); gsm[ri1 * 64 + bq * 4 + 0] = u.x; gsm[ri1 * 64 + bq * 4 + 1] = u.y;
            u = unpack2(acc2[1][1]); gsm[ri1 * 64 + bq * 4 + 2] = u.x; gsm[ri1 * 64 + bq * 4 + 3] = u.y;
        }
        __syncthreads();

#pragma unroll
        for (int r = 0; r < 2; r++) {
            const int it = tid + r * 128;
            const int j = it >> 6, b = it & 63;
            float gi = gsm[(0 * 4 + j) * 64 + b];
            float gf = gsm[(1 * 4 + j) * 64 + b];
            float gg = gsm[(2 * 4 + j) * 64 + b];
            float go = gsm[(3 * 4 + j) * 64 + b];
            float i_ = 1.f / (1.f + expf(-gi));
            float f_ = 1.f / (1.f + expf(-gf));
            float o_ = 1.f / (1.f + expf(-go));
            float g_ = tanhf(gg);
            float c_old = csm[j * 64 + b];
            float c_new = f_ * c_old + i_ * g_;
            float h_new = o_ * tanhf(c_new);
            bool  m = (tstep < len_sm[b]);
            float h_old = __ldcg(&hgl[(s4 + j) * 64 + b]);
            float c_out = m ? c_new : c_old;
            float h_out = m ? h_new : h_old;
            csm[j * 64 + b] = c_out;
            __stcg(&hgln[(s4 + j) * 64 + b], h_out);
            g_hout[((size_t)(dir * SEQ + tstep) * HID + (s4 + j)) * 64 + b] = h_out;
        }
        grid_barrier(gridDim.x);
    }
}

// ---------------- Kernel 3: logits = [h_f;h_b] @ W_clf^T + b_clf ----------------
__global__ __launch_bounds__(256) void clf_kernel(
    const float* __restrict__ Wclf, const float* __restrict__ bclf,
    float* __restrict__ out)
{
    __shared__ float Ws[32 * 65];
    __shared__ __align__(16) float hs[64 * 64];
    const int t   = blockIdx.x;
    const int tid = threadIdx.x;
    const int n   = tid & 31;
    const int bg  = tid >> 5;

    u64 acc2[4];
#pragma unroll
    for (int i = 0; i < 4; i++) acc2[i] = 0ull;

    for (int ch = 0; ch < 8; ch++) {
        const int dir = ch >> 2;
        const int jbase = (ch & 3) * 64;
        for (int l = tid; l < 2048; l += 256) {
            int nn = l >> 6, jj = l & 63;
            Ws[nn * 65 + jj] = Wclf[nn * 512 + dir * 256 + jbase + jj];
        }
        const float* hsrc = g_hout + ((size_t)(dir * SEQ + t) * HID + jbase) * 64;
#pragma unroll
        for (int r = 0; r < 4; r++)
            ((float4*)hs)[tid + r * 256] = __ldg(((const float4*)hsrc) + tid + r * 256);
        __syncthreads();
#pragma unroll 16
        for (int jj = 0; jj < 64; jj++) {
            u64 wd = dup2(Ws[n * 65 + jj]);
            ulonglong2 hA = *(const ulonglong2*)&hs[jj * 64 + bg * 8];
            ulonglong2 hB = *(const ulonglong2*)&hs[jj * 64 + bg * 8 + 4];
            acc2[0] = ffma2(wd, hA.x, acc2[0]);
            acc2[1] = ffma2(wd, hA.y, acc2[1]);
            acc2[2] = ffma2(wd, hB.x, acc2[2]);
            acc2[3] = ffma2(wd, hB.y, acc2[3]);
        }
        __syncthreads();
    }
    const float bias = bclf[n];
    float accf[8];
    { float2 u;
      u = unpack2(acc2[0]); accf[0] = u.x; accf[1] = u.y;
      u = unpack2(acc2[1]); accf[2] = u.x; accf[3] = u.y;
      u = unpack2(acc2[2]); accf[4] = u.x; accf[5] = u.y;
      u = unpack2(acc2[3]); accf[6] = u.x; accf[7] = u.y; }
#pragma unroll
    for (int bb = 0; bb < 8; bb++) {
        int b = bg * 8 + bb;
        out[((size_t)b * SEQ + t) * NK + n] = accf[bb] + bias;
    }
}

// ---------------- Kernel 4: Viterbi decode ----------------
__global__ __launch_bounds__(32) void viterbi_kernel(
    const float* __restrict__ logits, const int* __restrict__ lengths,
    const float* __restrict__ startt, const float* __restrict__ endt,
    const float* __restrict__ trans, float* __restrict__ preds, int write_preds)
{
    __shared__ unsigned char hist[511][32];
    const int b = blockIdx.x;
    const int j = threadIdx.x;
    const int len = lengths[b];

    float tcol[32];
#pragma unroll
    for (int i = 0; i < 32; i++) tcol[i] = trans[i * 32 + j];

    const float* lg = logits + (size_t)b * SEQ * NK;
    float score = startt[j] + lg[j];
    float e_next = lg[NK + j];

    for (int t = 1; t < SEQ; t++) {
        float e = e_next;
        if (t + 1 < SEQ) e_next = lg[(t + 1) * NK + j];

        float bv[16]; int bi[16];
#pragma unroll
        for (int i = 0; i < 16; i++) {
            float v0 = __shfl_sync(0xffffffffu, score, 2 * i)     + tcol[2 * i];
            float v1 = __shfl_sync(0xffffffffu, score, 2 * i + 1) + tcol[2 * i + 1];
            bool tt = v1 > v0;
            bv[i] = tt ? v1 : v0;
            bi[i] = tt ? 2 * i + 1 : 2 * i;
        }
#pragma unroll
        for (int s2 = 8; s2 >= 1; s2 >>= 1) {
#pragma unroll
            for (int i = 0; i < 8; i++) {
                if (i < s2) {
                    bool tt = bv[i + s2] > bv[i];
                    bv[i] = tt ? bv[i + s2] : bv[i];
                    bi[i] = tt ? bi[i + s2] : bi[i];
                }
            }
        }
        float nscore = bv[0] + e;
        int   arg    = bi[0];
        bool m = (t < len);
        hist[t - 1][j] = (unsigned char)(m ? arg : j);
        score = m ? nscore : score;
    }
    score += endt[j];

    float bvv = score; int bii = j;
#pragma unroll
    for (int off = 16; off; off >>= 1) {
        float ov = __shfl_xor_sync(0xffffffffu, bvv, off);
        int   oi = __shfl_xor_sync(0xffffffffu, bii, off);
        if (ov > bvv || (ov == bvv && oi < bii)) { bvv = ov; bii = oi; }
    }
    __syncwarp();

    if (write_preds && j == 0) {
        int tag = bii;
        float* pp = preds + (size_t)b * SEQ;
        for (int t = SEQ - 2; t >= 0; t--) {
            pp[t + 1] = (float)(((t + 1) < len) ? tag : 0);
            tag = hist[t][tag];
        }
        pp[0] = (float)((0 < len) ? tag : 0);
    }
}

// ---------------- launch ----------------
extern "C" void kernel_launch(void* const* d_in, const int* in_sizes, int n_in,
                              void* d_out, int out_size)
{
    const float* x     = (const float*)d_in[0];
    const int*   lens  = (const int*)d_in[1];
    const float* Wih_f = (const float*)d_in[3];
    const float* Whh_f = (const float*)d_in[4];
    const float* b_f   = (const float*)d_in[5];
    const float* Wih_b = (const float*)d_in[6];
    const float* Whh_b = (const float*)d_in[7];
    const float* b_b   = (const float*)d_in[8];
    const float* W_clf = (const float*)d_in[9];
    const float* b_clf = (const float*)d_in[10];
    const float* st_t  = (const float*)d_in[11];
    const float* en_t  = (const float*)d_in[12];
    const float* trans = (const float*)d_in[13];
    float* out = (float*)d_out;

    __nv_bfloat16 *xhi, *xlo, *whi, *wlo;
    cudaGetSymbolAddress((void**)&xhi, g_xhi);
    cudaGetSymbolAddress((void**)&xlo, g_xlo);
    cudaGetSymbolAddress((void**)&whi, g_whi);
    cudaGetSymbolAddress((void**)&wlo, g_wlo);

    split_kernel<<<2048, 256>>>(x, xhi, xlo, 32768 * 512);
    split_kernel<<<128, 256>>>(Wih_f, whi, wlo, 1024 * 512);
    split_kernel<<<128, 256>>>(Wih_b, whi + (size_t)1024 * 512, wlo + (size_t)1024 * 512, 1024 * 512);

    gemm_xp_mma_kernel<<<dim3(16, 256), 256>>>(b_f, b_b);

    lstm_kernel<<<128, 128>>>(Whh_f, Whh_b, lens);
    clf_kernel<<<512, 256>>>(W_clf, b_clf, out);

    const int logits_elems = BATCH * SEQ * NK;      // 1048576
    const int preds_elems  = BATCH * SEQ;           // 32768
    int wp = (out_size >= logits_elems + preds_elems) ? 1 : 0;
    viterbi_kernel<<<64, 32>>>(out, lens, st_t, en_t, trans, out + logits_elems, wp);
}